// round 15
// baseline (speedup 1.0000x reference)
#include <cuda_runtime.h>
#include <cuda_bf16.h>

#define NPTS 8192
#define MAXN 128
#define NC 8
#define NCELLS 512          // 8^3
#define CUT2 0.015625f      // 0.125^2, exact in fp32
#define WPB 8               // warps per block; 2 rows per warp
#define TPB (WPB * 32)      // 256
#define NB (NPTS / (2 * WPB))  // 512 blocks, co-resident (<= 148*4)
#define CAP 1536            // staged-candidate capacity per block
#define SEGMAX 64

// Scratch (no allocations allowed). Zero-initialized at module load.
__device__ int      g_count[NCELLS];   // histogram; reset in-kernel each run
__device__ float4   g_spos[NPTS];      // cell-sorted {x,y,z, idx-as-float-bits}
__device__ unsigned g_bar;             // monotonic grid-barrier ticket

__device__ __forceinline__ int cell_x(float v) {
    // v in [0,1): v*8 is an exact exponent shift in fp32; trunc == floor.
    int c = (int)(v * 8.0f);
    return c < 0 ? 0 : (c > 7 ? 7 : c);
}

// Grid barrier for a co-resident grid of nb blocks. Monotonic ticket ->
// counter is a multiple of nb at rest -> safe across graph replays.
__device__ __forceinline__ void grid_barrier(unsigned nb) {
    __syncthreads();
    if (threadIdx.x == 0) {
        __threadfence();
        const unsigned ticket = atomicAdd(&g_bar, 1u);
        const unsigned target = (ticket / nb + 1u) * nb;
        volatile unsigned* p = &g_bar;
        while (*p < target) { __nanosleep(32); }
    }
    __syncthreads();
}

// ---- fallback helpers (R10-proven direct sel loop) ----
__device__ __forceinline__ void make_window(const int* __restrict__ s_start,
                                            int cx, int cy, int cz,
                                            int o[10], int dlt[9]) {
    const int cx0 = cx > 0 ? cx - 1 : 0;
    const int cx1 = cx < 7 ? cx + 1 : 7;
    o[0] = 0;
    #pragma unroll
    for (int seg = 0; seg < 9; seg++) {
        const int zz = cz - 1 + seg / 3;
        const int yy = cy - 1 + seg % 3;
        const bool val = (unsigned)zz < 8u && (unsigned)yy < 8u;
        const int base = val ? (zz * NC + yy) * NC : 0;
        const int s = s_start[base + cx0];
        const int e = val ? s_start[base + cx1 + 1] : s;
        dlt[seg] = s - o[seg];
        o[seg + 1] = o[seg] + (e - s);
    }
}
__device__ __forceinline__ int sel_idx(int k, const int o[10], const int dlt[9]) {
    int d = dlt[0];
    #pragma unroll
    for (int i = 1; i < 9; i++)
        d = (k >= o[i]) ? dlt[i] : d;
    return k + d;
}

__global__ void __launch_bounds__(TPB, 4)
fused_kernel(const float* __restrict__ pos,
             float* __restrict__ out_idx,    // [NPTS, MAXN] float32
             float* __restrict__ out_cell,   // [NPTS, MAXN, 3] float32 (zeros)
             int* __restrict__ out_max)      // float32 bits, int atomicMax
{
    __shared__ unsigned bits[WPB][2][NPTS / 32];   // 16KB
    __shared__ int    s_start[NCELLS + 1];         // 2KB
    __shared__ int    wsum[8];
    __shared__ float4 s_cand[CAP];                 // 24KB staged candidates
    __shared__ int    seg_src[SEGMAX], seg_dst[SEGMAX], seg_len[SEGMAX];
    __shared__ int    s_bx[6];                     // xm,xM,ym,yM,zm,zM
    __shared__ int    s_T, s_nseg;

    const int tid  = threadIdx.x;
    const int warp = tid >> 5;
    const int lane = tid & 31;
    const int gi   = blockIdx.x * TPB + tid;

    // ---- phase 1: histogram (first 8192 threads own one point each) ----
    float px = 0.f, py = 0.f, pzz = 0.f;
    int c = 0, rank = 0;
    const bool own = gi < NPTS;
    if (own) {
        px  = pos[3 * gi + 0];
        py  = pos[3 * gi + 1];
        pzz = pos[3 * gi + 2];
        c = (cell_x(pzz) * NC + cell_x(py)) * NC + cell_x(px);
        if (gi == 0) *out_max = 0;                 // 0x0 == 0.0f
        rank = atomicAdd(&g_count[c], 1);
    }

    // flat zeroing of cell_indices (12MB) across all threads
    {
        float4* cp = (float4*)out_cell;
        const float4 z4 = make_float4(0.f, 0.f, 0.f, 0.f);
        #pragma unroll
        for (int t = 0; t < 6; t++)
            cp[(size_t)t * (NB * TPB) + gi] = z4;
    }

    grid_barrier(NB);                              // histogram complete

    // ---- phase 2: redundant block-local scan of 512 cells (2 per thread) ----
    {
        const int c0 = g_count[2 * tid];
        const int c1 = g_count[2 * tid + 1];
        const int s  = c0 + c1;
        int v = s;
        #pragma unroll
        for (int d = 1; d < 32; d <<= 1) {
            const int u = __shfl_up_sync(0xffffffffu, v, d);
            if (lane >= d) v += u;
        }
        if (lane == 31) wsum[warp] = v;
        __syncthreads();
        if (warp == 0 && lane < 8) {
            int w = wsum[lane];
            #pragma unroll
            for (int d = 1; d < 8; d <<= 1) {
                const int u = __shfl_up_sync(0xffu, w, d);
                if (lane >= d) w += u;
            }
            wsum[lane] = w;
        }
        __syncthreads();
        const int incl = v + (warp > 0 ? wsum[warp - 1] : 0);
        const int excl = incl - s;
        s_start[2 * tid]     = excl;
        s_start[2 * tid + 1] = excl + c0;
        if (tid == TPB - 1) s_start[NCELLS] = incl;
    }
    __syncthreads();

    // ---- phase 3: cursor-free scatter ----
    if (own)
        g_spos[s_start[c] + rank] = make_float4(px, py, pzz, __int_as_float(gi));

    grid_barrier(NB);                              // sorted array ready

    // reset histogram for the next graph replay
    if (gi < NCELLS) g_count[gi] = 0;

    // ---- phase 4a: block-union window + cooperative staging ----
    if (tid == 0) {
        s_bx[0] = 8; s_bx[1] = -1;   // xm, xM
        s_bx[2] = 8; s_bx[3] = -1;   // ym, yM
        s_bx[4] = 8; s_bx[5] = -1;   // zm, zM
    }
    // zero both bitsets (per warp, 128-bit stores)
    {
        uint4* bz = (uint4*)&bits[warp][0][0];
        const uint4 z4 = make_uint4(0u, 0u, 0u, 0u);
        #pragma unroll
        for (int t = 0; t < 4; t++)
            bz[t * 32 + lane] = z4;
    }
    __syncthreads();
    if (tid < 2 * WPB) {
        const float4 p = g_spos[blockIdx.x * (2 * WPB) + tid];
        atomicMin(&s_bx[0], cell_x(p.x)); atomicMax(&s_bx[1], cell_x(p.x));
        atomicMin(&s_bx[2], cell_x(p.y)); atomicMax(&s_bx[3], cell_x(p.y));
        atomicMin(&s_bx[4], cell_x(p.z)); atomicMax(&s_bx[5], cell_x(p.z));
    }
    __syncthreads();
    if (tid == 0) {
        const int x0 = max(s_bx[0] - 1, 0), x1 = min(s_bx[1] + 1, 7);
        const int y0 = max(s_bx[2] - 1, 0), y1 = min(s_bx[3] + 1, 7);
        const int z0 = max(s_bx[4] - 1, 0), z1 = min(s_bx[5] + 1, 7);
        int nseg = 0, T = 0;
        for (int zz = z0; zz <= z1; zz++)
            for (int yy = y0; yy <= y1; yy++) {
                const int base = (zz * NC + yy) * NC;
                const int s = s_start[base + x0];
                const int e = s_start[base + x1 + 1];
                seg_src[nseg] = s; seg_dst[nseg] = T; seg_len[nseg] = e - s;
                T += e - s; nseg++;
            }
        s_nseg = nseg;
        s_T = (T <= CAP) ? T : -1;                 // -1 -> fallback path
    }
    __syncthreads();

    const int T = s_T;
    if (T >= 0) {
        const int nseg = s_nseg;
        for (int sg = 0; sg < nseg; sg++) {
            const int len = seg_len[sg], src = seg_src[sg], dst = seg_dst[sg];
            for (int k = tid; k < len; k += TPB)
                s_cand[dst + k] = g_spos[src + k];
        }
    }
    __syncthreads();

    // ---- phase 4b: per-warp pair test ----
    const int s0 = (blockIdx.x * WPB + warp) * 2;
    const float4 A = g_spos[s0];
    const float4 B = g_spos[s0 + 1];
    const int rowA = __float_as_int(A.w);
    const int rowB = __float_as_int(B.w);

    if (T >= 0) {
        // fast path: linear LDS over the staged block-union candidates
        #pragma unroll 4
        for (int k = lane; k < T; k += 32) {
            const float4 q = s_cand[k];
            const int j = __float_as_int(q.w);
            // exact left-to-right f32, no FMA (bit-matches reference)
            const float axd = __fsub_rn(q.x, A.x);
            const float ayd = __fsub_rn(q.y, A.y);
            const float azd = __fsub_rn(q.z, A.z);
            const float dA = __fadd_rn(__fadd_rn(__fmul_rn(axd, axd),
                                                 __fmul_rn(ayd, ayd)),
                                       __fmul_rn(azd, azd));
            const float bxd = __fsub_rn(q.x, B.x);
            const float byd = __fsub_rn(q.y, B.y);
            const float bzd = __fsub_rn(q.z, B.z);
            const float dB = __fadd_rn(__fadd_rn(__fmul_rn(bxd, bxd),
                                                 __fmul_rn(byd, byd)),
                                       __fmul_rn(bzd, bzd));
            if (dA <= CUT2 && j != rowA)
                atomicOr(&bits[warp][0][j >> 5], 1u << (j & 31));
            if (dB <= CUT2 && j != rowB)
                atomicOr(&bits[warp][1][j >> 5], 1u << (j & 31));
        }
    } else {
        // fallback (rare): per-row direct sel loops over own 3x3 window
        #pragma unroll
        for (int r = 0; r < 2; r++) {
            const float4 P = r ? B : A;
            const int row = r ? rowB : rowA;
            int o[10], dlt[9];
            make_window(s_start, cell_x(P.x), cell_x(P.y), cell_x(P.z), o, dlt);
            const int Tw = o[9];
            #pragma unroll 4
            for (int k = lane; k < Tw; k += 32) {
                const float4 q = g_spos[sel_idx(k, o, dlt)];
                const int j = __float_as_int(q.w);
                const float dx = __fsub_rn(q.x, P.x);
                const float dy = __fsub_rn(q.y, P.y);
                const float dz = __fsub_rn(q.z, P.z);
                const float d2 = __fadd_rn(__fadd_rn(__fmul_rn(dx, dx),
                                                     __fmul_rn(dy, dy)),
                                           __fmul_rn(dz, dz));
                if (d2 <= CUT2 && j != row)
                    atomicOr(&bits[warp][r][j >> 5], 1u << (j & 31));
            }
        }
    }
    __syncwarp();

    // ---- ordered emission per row; 1 global atomicMax per warp ----
    int maxtot = 0;
    #pragma unroll
    for (int r = 0; r < 2; r++) {
        const int row = r ? rowB : rowA;
        unsigned myw[8];
        int csum = 0;
        #pragma unroll
        for (int t = 0; t < 8; t++) {
            myw[t] = bits[warp][r][lane * 8 + t];
            csum += __popc(myw[t]);
        }
        int x = csum;
        #pragma unroll
        for (int d = 1; d < 32; d <<= 1) {
            const int v = __shfl_up_sync(0xffffffffu, x, d);
            if (lane >= d) x += v;
        }
        int off = x - csum;
        const int total = __shfl_sync(0xffffffffu, x, 31);
        maxtot = max(maxtot, total);

        float* rowp = out_idx + (size_t)row * MAXN;
        #pragma unroll
        for (int t = 0; t < 8; t++) {
            unsigned m = myw[t];
            const int base = (lane * 8 + t) * 32;
            while (m) {
                const int b = __ffs(m) - 1;
                m &= m - 1;
                if (off < MAXN) rowp[off] = (float)(base + b);
                off++;
            }
        }
        const int st = total < MAXN ? total : MAXN;
        for (int k = st + lane; k < MAXN; k += 32)
            rowp[k] = -1.0f;
    }
    if (lane == 0) atomicMax(out_max, __float_as_int((float)maxtot));
}

extern "C" void kernel_launch(void* const* d_in, const int* in_sizes, int n_in,
                              void* d_out, int out_size)
{
    const float* pos = (const float*)d_in[0];
    float* out = (float*)d_out;

    const size_t toidx_elems = (size_t)NPTS * MAXN;      // 1,048,576
    const size_t cell_elems  = (size_t)NPTS * MAXN * 3;  // 3,145,728
    int* out_max = (int*)(out + toidx_elems + cell_elems);

    fused_kernel<<<NB, TPB>>>(pos, out, out + toidx_elems, out_max);
}

// round 16
// speedup vs baseline: 1.1825x; 1.1825x over previous
#include <cuda_runtime.h>
#include <cuda_bf16.h>

#define NPTS 8192
#define MAXN 128
#define NC 8
#define NCELLS 512          // 8^3
#define CUT2 0.015625f      // 0.125^2, exact in fp32
#define WPB 8               // warps per block; 2 rows per warp
#define TPB (WPB * 32)      // 256
#define NBLK 592            // 148 SMs x 4 blocks: perfectly balanced, co-resident
#define NPAIR (NPTS / 2)    // 4096 row-pairs
#define NT (NBLK * TPB)     // total threads

// Scratch (no allocations allowed). Zero-initialized at module load.
__device__ int      g_count[NCELLS];   // histogram; reset in-kernel each run
__device__ float4   g_spos[NPTS];      // cell-sorted {x,y,z, idx-as-float-bits}
__device__ unsigned g_bar;             // monotonic grid-barrier ticket

__device__ __forceinline__ int cell_x(float v) {
    // v in [0,1): v*8 is an exact exponent shift in fp32; trunc == floor.
    int c = (int)(v * 8.0f);
    return c < 0 ? 0 : (c > 7 ? 7 : c);
}

// Grid barrier for a co-resident grid of nb blocks. Monotonic ticket ->
// counter is a multiple of nb at rest -> safe across graph replays.
__device__ __forceinline__ void grid_barrier(unsigned nb) {
    __syncthreads();
    if (threadIdx.x == 0) {
        __threadfence();
        const unsigned ticket = atomicAdd(&g_bar, 1u);
        const unsigned target = (ticket / nb + 1u) * nb;
        volatile unsigned* p = &g_bar;
        while (*p < target) { __nanosleep(32); }
    }
    __syncthreads();
}

// Build the 9-segment window (registers only; fully unrolled)
__device__ __forceinline__ void make_window(const int* __restrict__ s_start,
                                            int cx, int cy, int cz,
                                            int o[10], int dlt[9]) {
    const int cx0 = cx > 0 ? cx - 1 : 0;
    const int cx1 = cx < 7 ? cx + 1 : 7;
    o[0] = 0;
    #pragma unroll
    for (int seg = 0; seg < 9; seg++) {
        const int zz = cz - 1 + seg / 3;
        const int yy = cy - 1 + seg % 3;
        const bool val = (unsigned)zz < 8u && (unsigned)yy < 8u;
        const int base = val ? (zz * NC + yy) * NC : 0;
        const int s = s_start[base + cx0];
        const int e = val ? s_start[base + cx1 + 1] : s;
        dlt[seg] = s - o[seg];
        o[seg + 1] = o[seg] + (e - s);
    }
}

// Branchless map: flat position k -> sorted-array index
__device__ __forceinline__ int sel_idx(int k, const int o[10], const int dlt[9]) {
    int d = dlt[0];
    #pragma unroll
    for (int i = 1; i < 9; i++)
        d = (k >= o[i]) ? dlt[i] : d;
    return k + d;
}

__global__ void __launch_bounds__(TPB, 4)
fused_kernel(const float* __restrict__ pos,
             float* __restrict__ out_idx,    // [NPTS, MAXN] float32
             float* __restrict__ out_cell,   // [NPTS, MAXN, 3] float32 (zeros)
             int* __restrict__ out_max)      // float32 bits, int atomicMax
{
    __shared__ unsigned bits[WPB][2][NPTS / 32];   // 16KB
    __shared__ int s_start[NCELLS + 1];            // block-local cell offsets
    __shared__ int wsum[8];

    const int tid  = threadIdx.x;
    const int warp = tid >> 5;
    const int lane = tid & 31;
    const int gi   = blockIdx.x * TPB + tid;

    // ---- phase 1: histogram (first 8192 threads own one point each) ----
    float px = 0.f, py = 0.f, pzz = 0.f;
    int c = 0, rank = 0;
    const bool own = gi < NPTS;
    if (own) {
        px  = pos[3 * gi + 0];
        py  = pos[3 * gi + 1];
        pzz = pos[3 * gi + 2];
        c = (cell_x(pzz) * NC + cell_x(py)) * NC + cell_x(px);
        if (gi == 0) *out_max = 0;                 // 0x0 == 0.0f
        rank = atomicAdd(&g_count[c], 1);
    }

    grid_barrier(NBLK);                            // histogram complete

    // ---- phase 2: redundant block-local scan of 512 cells (2 per thread) ----
    {
        const int c0 = g_count[2 * tid];
        const int c1 = g_count[2 * tid + 1];
        const int s  = c0 + c1;
        int v = s;
        #pragma unroll
        for (int d = 1; d < 32; d <<= 1) {
            const int u = __shfl_up_sync(0xffffffffu, v, d);
            if (lane >= d) v += u;
        }
        if (lane == 31) wsum[warp] = v;
        __syncthreads();
        if (warp == 0 && lane < 8) {
            int w = wsum[lane];
            #pragma unroll
            for (int d = 1; d < 8; d <<= 1) {
                const int u = __shfl_up_sync(0xffu, w, d);
                if (lane >= d) w += u;
            }
            wsum[lane] = w;
        }
        __syncthreads();
        const int incl = v + (warp > 0 ? wsum[warp - 1] : 0);
        const int excl = incl - s;
        s_start[2 * tid]     = excl;
        s_start[2 * tid + 1] = excl + c0;
        if (tid == TPB - 1) s_start[NCELLS] = incl;
    }
    __syncthreads();

    // ---- phase 3: cursor-free scatter ----
    if (own)
        g_spos[s_start[c] + rank] = make_float4(px, py, pzz, __int_as_float(gi));

    grid_barrier(NBLK);                            // sorted array ready

    // reset histogram for the next graph replay
    if (gi < NCELLS) g_count[gi] = 0;

    // ---- phase 4: neighbor search, warp per PAIR, flat selected loop ----
    const int gw = blockIdx.x * WPB + warp;        // global warp id
    if (gw < NPAIR) {
        const int s0 = gw * 2;

        // zero both bitsets with 128-bit stores
        {
            uint4* bz = (uint4*)&bits[warp][0][0];
            const uint4 z4 = make_uint4(0u, 0u, 0u, 0u);
            #pragma unroll
            for (int t = 0; t < 4; t++)
                bz[t * 32 + lane] = z4;
        }

        const float4 A = g_spos[s0];
        const float4 B = g_spos[s0 + 1];
        const int rowA = __float_as_int(A.w);
        const int rowB = __float_as_int(B.w);

        const int cax = cell_x(A.x), cay = cell_x(A.y), caz = cell_x(A.z);
        const int cbx = cell_x(B.x), cby = cell_x(B.y), cbz = cell_x(B.z);
        __syncwarp();

        if (cax == cbx && cay == cby && caz == cbz) {
            int o[10], dlt[9];
            make_window(s_start, cax, cay, caz, o, dlt);
            const int T = o[9];
            #pragma unroll 4
            for (int k = lane; k < T; k += 32) {
                const float4 q = g_spos[sel_idx(k, o, dlt)];
                const int j = __float_as_int(q.w);
                // exact left-to-right f32, no FMA (bit-matches reference);
                // self-hit (d2 == 0) allowed -> self bit cleared post-loop
                const float axd = __fsub_rn(q.x, A.x);
                const float ayd = __fsub_rn(q.y, A.y);
                const float azd = __fsub_rn(q.z, A.z);
                const float dA = __fadd_rn(__fadd_rn(__fmul_rn(axd, axd),
                                                     __fmul_rn(ayd, ayd)),
                                           __fmul_rn(azd, azd));
                const float bxd = __fsub_rn(q.x, B.x);
                const float byd = __fsub_rn(q.y, B.y);
                const float bzd = __fsub_rn(q.z, B.z);
                const float dB = __fadd_rn(__fadd_rn(__fmul_rn(bxd, bxd),
                                                     __fmul_rn(byd, byd)),
                                           __fmul_rn(bzd, bzd));
                if (dA <= CUT2)
                    atomicOr(&bits[warp][0][j >> 5], 1u << (j & 31));
                if (dB <= CUT2)
                    atomicOr(&bits[warp][1][j >> 5], 1u << (j & 31));
            }
        } else {
            // rare (~6%): two flat passes, one per row
            #pragma unroll
            for (int r = 0; r < 2; r++) {
                const float4 P = r ? B : A;
                int o[10], dlt[9];
                make_window(s_start,
                            r ? cbx : cax, r ? cby : cay, r ? cbz : caz, o, dlt);
                const int T = o[9];
                #pragma unroll 4
                for (int k = lane; k < T; k += 32) {
                    const float4 q = g_spos[sel_idx(k, o, dlt)];
                    const int j = __float_as_int(q.w);
                    const float dx = __fsub_rn(q.x, P.x);
                    const float dy = __fsub_rn(q.y, P.y);
                    const float dz = __fsub_rn(q.z, P.z);
                    const float d2 = __fadd_rn(__fadd_rn(__fmul_rn(dx, dx),
                                                         __fmul_rn(dy, dy)),
                                               __fmul_rn(dz, dz));
                    if (d2 <= CUT2)
                        atomicOr(&bits[warp][r][j >> 5], 1u << (j & 31));
                }
            }
        }
        __syncwarp();

        // clear the self bits (INCLUDE_SELF = False)
        if (lane == 0) {
            bits[warp][0][rowA >> 5] &= ~(1u << (rowA & 31));
            bits[warp][1][rowB >> 5] &= ~(1u << (rowB & 31));
        }
        __syncwarp();

        // ---- ordered emission per row; 1 global atomicMax per warp ----
        int maxtot = 0;
        #pragma unroll
        for (int r = 0; r < 2; r++) {
            const int row = r ? rowB : rowA;
            unsigned myw[8];
            int csum = 0;
            #pragma unroll
            for (int t = 0; t < 8; t++) {
                myw[t] = bits[warp][r][lane * 8 + t];
                csum += __popc(myw[t]);
            }
            int x = csum;
            #pragma unroll
            for (int d = 1; d < 32; d <<= 1) {
                const int v = __shfl_up_sync(0xffffffffu, x, d);
                if (lane >= d) x += v;
            }
            int off = x - csum;
            const int total = __shfl_sync(0xffffffffu, x, 31);
            maxtot = max(maxtot, total);

            float* rowp = out_idx + (size_t)row * MAXN;
            #pragma unroll
            for (int t = 0; t < 8; t++) {
                unsigned m = myw[t];
                const int base = (lane * 8 + t) * 32;
                while (m) {
                    const int b = __ffs(m) - 1;
                    m &= m - 1;
                    if (off < MAXN) rowp[off] = (float)(base + b);
                    off++;
                }
            }
            const int st = total < MAXN ? total : MAXN;
            for (int k = st + lane; k < MAXN; k += 32)
                rowp[k] = -1.0f;
        }
        if (lane == 0) atomicMax(out_max, __float_as_int((float)maxtot));
    }

    // ---- tail: zero cell_indices (12MB) off the critical path ----
    {
        float4* cp = (float4*)out_cell;
        const float4 z4 = make_float4(0.f, 0.f, 0.f, 0.f);
        const int total4 = NPTS * MAXN * 3 / 4;    // 786432 float4
        for (int i = gi; i < total4; i += NT)
            cp[i] = z4;
    }
}

extern "C" void kernel_launch(void* const* d_in, const int* in_sizes, int n_in,
                              void* d_out, int out_size)
{
    const float* pos = (const float*)d_in[0];
    float* out = (float*)d_out;

    const size_t toidx_elems = (size_t)NPTS * MAXN;      // 1,048,576
    const size_t cell_elems  = (size_t)NPTS * MAXN * 3;  // 3,145,728
    int* out_max = (int*)(out + toidx_elems + cell_elems);

    fused_kernel<<<NBLK, TPB>>>(pos, out, out + toidx_elems, out_max);
}

// round 17
// speedup vs baseline: 1.1951x; 1.0107x over previous
#include <cuda_runtime.h>
#include <cuda_bf16.h>

#define NPTS 8192
#define MAXN 128
#define NC 8
#define NCELLS 512          // 8^3
#define CUT2 0.015625f      // 0.125^2, exact in fp32
#define WPB 8               // warps per block; 2 rows per warp
#define TPB (WPB * 32)      // 256
#define NBLK 592            // 148 SMs x 4 blocks: balanced, co-resident
#define NPAIR (NPTS / 2)    // 4096 row-pairs
#define NT (NBLK * TPB)     // total threads

// Scratch (no allocations allowed). Zero-initialized at module load.
__device__ int      g_count[NCELLS];   // histogram; reset in-kernel each run
__device__ float4   g_spos[NPTS];      // cell-sorted {x,y,z, idx-as-float-bits}
__device__ unsigned g_bar;             // monotonic grid-barrier ticket

__device__ __forceinline__ int cell_x(float v) {
    // v in [0,1): v*8 is an exact exponent shift in fp32; trunc == floor.
    int c = (int)(v * 8.0f);
    return c < 0 ? 0 : (c > 7 ? 7 : c);
}

// Grid barrier for a co-resident grid of nb blocks. Monotonic ticket ->
// counter is a multiple of nb at rest -> safe across graph replays.
__device__ __forceinline__ void grid_barrier(unsigned nb) {
    __syncthreads();
    if (threadIdx.x == 0) {
        __threadfence();
        const unsigned ticket = atomicAdd(&g_bar, 1u);
        const unsigned target = (ticket / nb + 1u) * nb;
        volatile unsigned* p = &g_bar;
        while (*p < target) { __nanosleep(16); }
    }
    __syncthreads();
}

// Build the 9-segment window (registers only; fully unrolled)
__device__ __forceinline__ void make_window(const int* __restrict__ s_start,
                                            int cx, int cy, int cz,
                                            int o[10], int dlt[9]) {
    const int cx0 = cx > 0 ? cx - 1 : 0;
    const int cx1 = cx < 7 ? cx + 1 : 7;
    o[0] = 0;
    #pragma unroll
    for (int seg = 0; seg < 9; seg++) {
        const int zz = cz - 1 + seg / 3;
        const int yy = cy - 1 + seg % 3;
        const bool val = (unsigned)zz < 8u && (unsigned)yy < 8u;
        const int base = val ? (zz * NC + yy) * NC : 0;
        const int s = s_start[base + cx0];
        const int e = val ? s_start[base + cx1 + 1] : s;
        dlt[seg] = s - o[seg];
        o[seg + 1] = o[seg] + (e - s);
    }
}

// Branchless map: flat position k -> sorted-array index
__device__ __forceinline__ int sel_idx(int k, const int o[10], const int dlt[9]) {
    int d = dlt[0];
    #pragma unroll
    for (int i = 1; i < 9; i++)
        d = (k >= o[i]) ? dlt[i] : d;
    return k + d;
}

__global__ void __launch_bounds__(TPB, 4)
fused_kernel(const float* __restrict__ pos,
             float* __restrict__ out_idx,    // [NPTS, MAXN] float32
             float* __restrict__ out_cell,   // [NPTS, MAXN, 3] float32 (zeros)
             int* __restrict__ out_max)      // float32 bits, int atomicMax
{
    __shared__ __align__(16) unsigned bits[WPB][2][NPTS / 32];   // 16KB
    __shared__ int s_start[NCELLS + 1];            // block-local cell offsets
    __shared__ int wsum[8];

    const int tid  = threadIdx.x;
    const int warp = tid >> 5;
    const int lane = tid & 31;
    const int gi   = blockIdx.x * TPB + tid;

    // ---- phase 1: histogram (first 8192 threads own one point each) ----
    float px = 0.f, py = 0.f, pzz = 0.f;
    int c = 0, rank = 0;
    const bool own = gi < NPTS;
    if (own) {
        px  = pos[3 * gi + 0];
        py  = pos[3 * gi + 1];
        pzz = pos[3 * gi + 2];
        c = (cell_x(pzz) * NC + cell_x(py)) * NC + cell_x(px);
        if (gi == 0) *out_max = 0;                 // 0x0 == 0.0f
        rank = atomicAdd(&g_count[c], 1);
    }

    grid_barrier(NBLK);                            // histogram complete

    // ---- phase 2: redundant block-local scan of 512 cells (2 per thread) ----
    {
        const int c0 = g_count[2 * tid];
        const int c1 = g_count[2 * tid + 1];
        const int s  = c0 + c1;
        int v = s;
        #pragma unroll
        for (int d = 1; d < 32; d <<= 1) {
            const int u = __shfl_up_sync(0xffffffffu, v, d);
            if (lane >= d) v += u;
        }
        if (lane == 31) wsum[warp] = v;
        __syncthreads();
        if (warp == 0 && lane < 8) {
            int w = wsum[lane];
            #pragma unroll
            for (int d = 1; d < 8; d <<= 1) {
                const int u = __shfl_up_sync(0xffu, w, d);
                if (lane >= d) w += u;
            }
            wsum[lane] = w;
        }
        __syncthreads();
        const int incl = v + (warp > 0 ? wsum[warp - 1] : 0);
        const int excl = incl - s;
        s_start[2 * tid]     = excl;
        s_start[2 * tid + 1] = excl + c0;
        if (tid == TPB - 1) s_start[NCELLS] = incl;
    }
    __syncthreads();

    // ---- phase 3: cursor-free scatter ----
    if (own)
        g_spos[s_start[c] + rank] = make_float4(px, py, pzz, __int_as_float(gi));

    grid_barrier(NBLK);                            // sorted array ready

    // reset histogram for the next graph replay
    if (gi < NCELLS) g_count[gi] = 0;

    // ---- phase 4: neighbor search, warp per PAIR, flat selected loop ----
    const int gw = blockIdx.x * WPB + warp;        // global warp id
    if (gw < NPAIR) {
        const int s0 = gw * 2;

        // zero both bitsets with 128-bit stores
        {
            uint4* bz = (uint4*)&bits[warp][0][0];
            const uint4 z4 = make_uint4(0u, 0u, 0u, 0u);
            #pragma unroll
            for (int t = 0; t < 4; t++)
                bz[t * 32 + lane] = z4;
        }

        const float4 A = g_spos[s0];
        const float4 B = g_spos[s0 + 1];
        const int rowA = __float_as_int(A.w);
        const int rowB = __float_as_int(B.w);

        const int cax = cell_x(A.x), cay = cell_x(A.y), caz = cell_x(A.z);
        const int cbx = cell_x(B.x), cby = cell_x(B.y), cbz = cell_x(B.z);
        __syncwarp();

        if (cax == cbx && cay == cby && caz == cbz) {
            int o[10], dlt[9];
            make_window(s_start, cax, cay, caz, o, dlt);
            const int T = o[9];
            #pragma unroll 4
            for (int k = lane; k < T; k += 32) {
                const float4 q = g_spos[sel_idx(k, o, dlt)];
                const int j = __float_as_int(q.w);
                // exact left-to-right f32, no FMA (bit-matches reference);
                // self-hit (d2 == 0) allowed -> self bit cleared post-loop
                const float axd = __fsub_rn(q.x, A.x);
                const float ayd = __fsub_rn(q.y, A.y);
                const float azd = __fsub_rn(q.z, A.z);
                const float dA = __fadd_rn(__fadd_rn(__fmul_rn(axd, axd),
                                                     __fmul_rn(ayd, ayd)),
                                           __fmul_rn(azd, azd));
                const float bxd = __fsub_rn(q.x, B.x);
                const float byd = __fsub_rn(q.y, B.y);
                const float bzd = __fsub_rn(q.z, B.z);
                const float dB = __fadd_rn(__fadd_rn(__fmul_rn(bxd, bxd),
                                                     __fmul_rn(byd, byd)),
                                           __fmul_rn(bzd, bzd));
                if (dA <= CUT2)
                    atomicOr(&bits[warp][0][j >> 5], 1u << (j & 31));
                if (dB <= CUT2)
                    atomicOr(&bits[warp][1][j >> 5], 1u << (j & 31));
            }
        } else {
            // rare (~6%): two flat passes, one per row
            #pragma unroll
            for (int r = 0; r < 2; r++) {
                const float4 P = r ? B : A;
                int o[10], dlt[9];
                make_window(s_start,
                            r ? cbx : cax, r ? cby : cay, r ? cbz : caz, o, dlt);
                const int T = o[9];
                #pragma unroll 4
                for (int k = lane; k < T; k += 32) {
                    const float4 q = g_spos[sel_idx(k, o, dlt)];
                    const int j = __float_as_int(q.w);
                    const float dx = __fsub_rn(q.x, P.x);
                    const float dy = __fsub_rn(q.y, P.y);
                    const float dz = __fsub_rn(q.z, P.z);
                    const float d2 = __fadd_rn(__fadd_rn(__fmul_rn(dx, dx),
                                                         __fmul_rn(dy, dy)),
                                               __fmul_rn(dz, dz));
                    if (d2 <= CUT2)
                        atomicOr(&bits[warp][r][j >> 5], 1u << (j & 31));
                }
            }
        }
        __syncwarp();

        // clear the self bits (INCLUDE_SELF = False)
        if (lane == 0) {
            bits[warp][0][rowA >> 5] &= ~(1u << (rowA & 31));
            bits[warp][1][rowB >> 5] &= ~(1u << (rowB & 31));
        }
        __syncwarp();

        // ---- ordered emission per row via SMEM staging + STG.128 ----
        int maxtot = 0;
        #pragma unroll
        for (int r = 0; r < 2; r++) {
            const int row = r ? rowB : rowA;
            unsigned myw[8];
            int csum = 0;
            #pragma unroll
            for (int t = 0; t < 8; t++) {
                myw[t] = bits[warp][r][lane * 8 + t];
                csum += __popc(myw[t]);
            }
            int x = csum;
            #pragma unroll
            for (int d = 1; d < 32; d <<= 1) {
                const int v = __shfl_up_sync(0xffffffffu, x, d);
                if (lane >= d) x += v;
            }
            int off = x - csum;
            const int total = __shfl_sync(0xffffffffu, x, 31);
            maxtot = max(maxtot, total);

            // bitset words for this row are now in registers -> reuse the
            // 1KB region as a 128-float staging buffer
            float*  stage  = (float*)&bits[warp][r][0];
            float4* stage4 = (float4*)stage;
            __syncwarp();                          // all myw reads done
            stage4[lane] = make_float4(-1.f, -1.f, -1.f, -1.f);
            __syncwarp();
            #pragma unroll
            for (int t = 0; t < 8; t++) {
                unsigned m = myw[t];
                const int base = (lane * 8 + t) * 32;
                while (m) {
                    const int b = __ffs(m) - 1;
                    m &= m - 1;
                    if (off < MAXN) stage[off] = (float)(base + b);
                    off++;
                }
            }
            __syncwarp();
            // one coalesced 512B wave per row
            float4* rowp4 = (float4*)(out_idx + (size_t)row * MAXN);
            rowp4[lane] = stage4[lane];
        }
        if (lane == 0) atomicMax(out_max, __float_as_int((float)maxtot));
    }

    // ---- tail: zero cell_indices (12MB) off the critical path ----
    {
        float4* cp = (float4*)out_cell;
        const float4 z4 = make_float4(0.f, 0.f, 0.f, 0.f);
        const int total4 = NPTS * MAXN * 3 / 4;    // 786432 float4
        for (int i = gi; i < total4; i += NT)
            cp[i] = z4;
    }
}

extern "C" void kernel_launch(void* const* d_in, const int* in_sizes, int n_in,
                              void* d_out, int out_size)
{
    const float* pos = (const float*)d_in[0];
    float* out = (float*)d_out;

    const size_t toidx_elems = (size_t)NPTS * MAXN;      // 1,048,576
    const size_t cell_elems  = (size_t)NPTS * MAXN * 3;  // 3,145,728
    int* out_max = (int*)(out + toidx_elems + cell_elems);

    fused_kernel<<<NBLK, TPB>>>(pos, out, out + toidx_elems, out_max);
}